// round 15
// baseline (speedup 1.0000x reference)
#include <cuda_runtime.h>
#include <cuda_fp16.h>
#include <cstdint>

#define BATCH 8
#define SLEN 1024
#define DMODEL 1024
#define NHEADS 16
#define HDIM 64
#define MROWS (BATCH * SLEN)       // 8192
#define QKV_N (3 * DMODEL)         // 3072
#define LN_EPS 1e-5f
// SM_SCALE * log2(e) folded into Q fragments: scores live in log2 domain.
#define QSCALE_LOG2E 0.045084220f  // 0.03125 * 1.4426950408889634

// Scratch (static device globals: allocation-free rule)
__device__ __half g_xh[(size_t)MROWS * DMODEL];
__device__ __half g_wqkv[(size_t)DMODEL * QKV_N];
__device__ __half g_wout[(size_t)DMODEL * DMODEL];
__device__ __half g_qkv[(size_t)MROWS * QKV_N];
__device__ __half g_attn[(size_t)MROWS * DMODEL];

// ---------------------------------------------------------------------------
// helpers
// ---------------------------------------------------------------------------
__device__ __forceinline__ uint32_t cvta_smem(const void* p) {
    uint32_t a;
    asm("{.reg .u64 t; cvta.to.shared.u64 t, %1; cvt.u32.u64 %0, t;}"
        : "=r"(a) : "l"(p));
    return a;
}
__device__ __forceinline__ void ldsm4(uint32_t a, uint32_t& r0, uint32_t& r1,
                                      uint32_t& r2, uint32_t& r3) {
    asm volatile("ldmatrix.sync.aligned.m8n8.x4.shared.b16 {%0,%1,%2,%3},[%4];"
                 : "=r"(r0), "=r"(r1), "=r"(r2), "=r"(r3) : "r"(a));
}
__device__ __forceinline__ void ldsm4t(uint32_t a, uint32_t& r0, uint32_t& r1,
                                       uint32_t& r2, uint32_t& r3) {
    asm volatile("ldmatrix.sync.aligned.m8n8.x4.trans.shared.b16 {%0,%1,%2,%3},[%4];"
                 : "=r"(r0), "=r"(r1), "=r"(r2), "=r"(r3) : "r"(a));
}
__device__ __forceinline__ void mma_fp16(float* c, const uint32_t* a,
                                         const uint32_t* b) {
    asm volatile(
        "mma.sync.aligned.m16n8k16.row.col.f32.f16.f16.f32 "
        "{%0,%1,%2,%3},{%4,%5,%6,%7},{%8,%9},{%0,%1,%2,%3};"
        : "+f"(c[0]), "+f"(c[1]), "+f"(c[2]), "+f"(c[3])
        : "r"(a[0]), "r"(a[1]), "r"(a[2]), "r"(a[3]), "r"(b[0]), "r"(b[1]));
}
// fp16-accumulator variant
__device__ __forceinline__ void mma_fp16h(uint32_t* c, const uint32_t* a,
                                          const uint32_t* b) {
    asm volatile(
        "mma.sync.aligned.m16n8k16.row.col.f16.f16.f16.f16 "
        "{%0,%1},{%2,%3,%4,%5},{%6,%7},{%0,%1};"
        : "+r"(c[0]), "+r"(c[1])
        : "r"(a[0]), "r"(a[1]), "r"(a[2]), "r"(a[3]), "r"(b[0]), "r"(b[1]));
}
__device__ __forceinline__ uint32_t pack_h2(float x, float y) {
    __half2 h = __floats2half2_rn(x, y);
    return *(uint32_t*)&h;
}

// ---------------------------------------------------------------------------
// fused fp32 -> fp16 conversion of x, Wqkv, Wout in one launch
// ---------------------------------------------------------------------------
#define N4_X   (MROWS * DMODEL / 4)              // 2,097,152
#define N4_WQ  (DMODEL * QKV_N / 4)              //   786,432
#define N4_WO  (DMODEL * DMODEL / 4)             //   262,144
#define N4_ALL (N4_X + N4_WQ + N4_WO)

__global__ __launch_bounds__(256) void cvt_all_kernel(
    const float4* __restrict__ x, const float4* __restrict__ wq,
    const float4* __restrict__ wo, uint2* __restrict__ xh,
    uint2* __restrict__ wqh, uint2* __restrict__ woh)
{
    int i = blockIdx.x * blockDim.x + threadIdx.x;
    if (i >= N4_ALL) return;
    const float4* src;
    uint2* dst;
    int j;
    if (i < N4_X)            { src = x;  dst = xh;  j = i; }
    else if (i < N4_X + N4_WQ) { src = wq; dst = wqh; j = i - N4_X; }
    else                     { src = wo; dst = woh; j = i - N4_X - N4_WQ; }
    float4 v = src[j];
    uint2 o;
    o.x = pack_h2(v.x, v.y);
    o.y = pack_h2(v.z, v.w);
    dst[j] = o;
}

// ---------------------------------------------------------------------------
// QKV GEMM: fp16 ACCUMULATORS, wide tiles. BM=128, BN=256, BK=32,
// 8 warps each owning 64x64 (8 LDSM feed 32 MMAs/k-step). 2 CTAs/SM.
// C = A@B + bias, fp16 out.
// ---------------------------------------------------------------------------
#define BM 128
#define HBN 256
#define BK 32
#define A_STR 40         // BK + 8 pad
#define HB_STR 264       // HBN + 8 pad
#define HABUF (BM * A_STR)                  // 5120 elems
#define HBBUF (BK * HB_STR)                 // 8448 elems
#define HGBUF_ELEMS (HABUF + HBBUF)         // 13568 elems = 27,136 B / buffer
#define HGSMEM_BYTES (2 * HGBUF_ELEMS * 2)  // 54,272 B

__global__ __launch_bounds__(256, 2) void mma_gemm_h(
    const __half* __restrict__ Ah, const __half* __restrict__ Bh,
    const float* __restrict__ bias, __half* __restrict__ Ch,
    int M, int N, int K)
{
    extern __shared__ __align__(16) __half dsm[];

    const int tid = threadIdx.x;
    const int lane = tid & 31;
    const int warp = tid >> 5;
    const int wm = warp >> 2;    // 0..1 -> 64 rows
    const int wn = warp & 3;     // 0..3 -> 64 cols
    const int bm0 = blockIdx.y * BM;
    const int bn0 = blockIdx.x * HBN;

    const int ar = tid >> 2;          // 0..63 (rows ar, ar+64)
    const int ac = (tid & 3) * 8;     // k offset
    const int br = tid >> 3;          // 0..31
    const int bc = (tid & 7) * 32;    // n offset (4 uint4)

    uint32_t acc[4][8][2];
    #pragma unroll
    for (int i = 0; i < 4; i++)
        #pragma unroll
        for (int j = 0; j < 8; j++) { acc[i][j][0] = 0u; acc[i][j][1] = 0u; }

    const __half* Ap = Ah + (size_t)(bm0 + ar) * K + ac;
    const __half* Bp = Bh + (size_t)br * N + bn0 + bc;

    uint4 pa[2], pb[4];
    pa[0] = *(const uint4*)(Ap);
    pa[1] = *(const uint4*)(Ap + (size_t)64 * K);
    #pragma unroll
    for (int j = 0; j < 4; j++)
        pb[j] = *(const uint4*)(Bp + 8 * j);

    const int iters = K / BK;
    for (int it = 0; it < iters; it++) {
        __half* buf = dsm + (it & 1) * HGBUF_ELEMS;
        __half* sA = buf;
        __half* sB = buf + HABUF;
        {   // stage prefetched tile
            uint2* d; const uint2* s;
            d = (uint2*)&sA[ar * A_STR + ac];        s = (const uint2*)&pa[0]; d[0]=s[0]; d[1]=s[1];
            d = (uint2*)&sA[(ar + 64) * A_STR + ac]; s = (const uint2*)&pa[1]; d[0]=s[0]; d[1]=s[1];
            #pragma unroll
            for (int j = 0; j < 4; j++) {
                d = (uint2*)&sB[br * HB_STR + bc + 8 * j];
                s = (const uint2*)&pb[j];
                d[0] = s[0]; d[1] = s[1];
            }
        }
        __syncthreads();

        if (it + 1 < iters) {   // prefetch next tile (overlaps with MMAs)
            const size_t ka = (size_t)(it + 1) * BK;
            pa[0] = *(const uint4*)(Ap + ka);
            pa[1] = *(const uint4*)(Ap + (size_t)64 * K + ka);
            const size_t kb = ka * N;
            #pragma unroll
            for (int j = 0; j < 4; j++)
                pb[j] = *(const uint4*)(Bp + kb + 8 * j);
        }

        #pragma unroll
        for (int kk = 0; kk < 2; kk++) {
            uint32_t a[4][4];
            const int arow = wm * 64 + (lane & 15);
            const int acol = kk * 16 + (lane >> 4) * 8;
            #pragma unroll
            for (int mt = 0; mt < 4; mt++)
                ldsm4(cvta_smem(&sA[(arow + mt * 16) * A_STR + acol]),
                      a[mt][0], a[mt][1], a[mt][2], a[mt][3]);
            const int brow = kk * 16 + (lane & 15);
            // consume B fragments immediately (keeps live regs low)
            #pragma unroll
            for (int ng = 0; ng < 4; ng++) {
                uint32_t b0, b1, b2, b3;
                const int bcol = wn * 64 + ng * 16 + (lane >> 4) * 8;
                ldsm4t(cvta_smem(&sB[brow * HB_STR + bcol]), b0, b1, b2, b3);
                uint32_t be[2] = {b0, b1}, bo[2] = {b2, b3};
                #pragma unroll
                for (int mt = 0; mt < 4; mt++) {
                    mma_fp16h(acc[mt][2*ng],   a[mt], be);
                    mma_fp16h(acc[mt][2*ng+1], a[mt], bo);
                }
            }
        }
        // next iter stores to the other buffer; top-of-iter sync orders it.
    }

    const int r0 = lane >> 2;
    const int cp = (lane & 3) * 2;
    #pragma unroll
    for (int mt = 0; mt < 4; mt++) {
        #pragma unroll
        for (int nt = 0; nt < 8; nt++) {
            const int gc = bn0 + wn * 64 + nt * 8 + cp;
            const float2 bv = *(const float2*)(bias + gc);
            #pragma unroll
            for (int h = 0; h < 2; h++) {
                const int gr = bm0 + wm * 64 + mt * 16 + r0 + h * 8;
                float2 f = __half22float2(*(__half2*)&acc[mt][nt][h]);
                *(uint32_t*)(Ch + (size_t)gr * N + gc) =
                    pack_h2(f.x + bv.x, f.y + bv.y);
            }
        }
    }
}

// ---------------------------------------------------------------------------
// Out-proj GEMM (fp32 accumulators, unchanged): BM=BN=128, BK=32, 2 CTAs/SM.
// C = A@B + bias + residual, fp32 out.
// ---------------------------------------------------------------------------
#define BN 128
#define B_STR 136       // BN + 8 pad
#define ABUF (BM * A_STR)                 // 5120 elems
#define BBUF (BK * B_STR)                 // 4352 elems
#define GBUF_ELEMS (ABUF + BBUF)          // 9472 elems = 18,944 B / buffer
#define GSMEM_BYTES (2 * GBUF_ELEMS * 2)  // 37,888 B

__global__ __launch_bounds__(256, 2) void mma_gemm(
    const __half* __restrict__ Ah, const __half* __restrict__ Bh,
    const float* __restrict__ bias, const float* __restrict__ res,
    float* __restrict__ C, int M, int N, int K)
{
    extern __shared__ __align__(16) __half dsm[];

    const int tid = threadIdx.x;
    const int lane = tid & 31;
    const int warp = tid >> 5;
    const int wm = warp >> 2;
    const int wn = warp & 3;
    const int bm0 = blockIdx.y * BM;
    const int bn0 = blockIdx.x * BN;

    const int ar = tid >> 2;          // 0..63 (rows ar, ar+64)
    const int ac = (tid & 3) * 8;     // k offset
    const int br = tid >> 3;          // 0..31
    const int bc = (tid & 7) * 16;    // n offset

    float acc[4][4][4];
    #pragma unroll
    for (int i = 0; i < 4; i++)
        #pragma unroll
        for (int j = 0; j < 4; j++)
            #pragma unroll
            for (int c = 0; c < 4; c++) acc[i][j][c] = 0.0f;

    const __half* Ap = Ah + (size_t)(bm0 + ar) * K + ac;
    const __half* Bp = Bh + (size_t)br * N + bn0 + bc;

    uint4 pa[2], pb[2];
    pa[0] = *(const uint4*)(Ap);
    pa[1] = *(const uint4*)(Ap + (size_t)64 * K);
    pb[0] = *(const uint4*)(Bp);
    pb[1] = *(const uint4*)(Bp + 8);

    const int iters = K / BK;
    for (int it = 0; it < iters; it++) {
        __half* buf = dsm + (it & 1) * GBUF_ELEMS;
        __half* sA = buf;
        __half* sB = buf + ABUF;
        {
            uint2* d; const uint2* s;
            d = (uint2*)&sA[ar * A_STR + ac];        s = (const uint2*)&pa[0]; d[0]=s[0]; d[1]=s[1];
            d = (uint2*)&sA[(ar + 64) * A_STR + ac]; s = (const uint2*)&pa[1]; d[0]=s[0]; d[1]=s[1];
            d = (uint2*)&sB[br * B_STR + bc];        s = (const uint2*)&pb[0]; d[0]=s[0]; d[1]=s[1];
            d = (uint2*)&sB[br * B_STR + bc + 8];    s = (const uint2*)&pb[1]; d[0]=s[0]; d[1]=s[1];
        }
        __syncthreads();

        if (it + 1 < iters) {
            const size_t ka = (size_t)(it + 1) * BK;
            pa[0] = *(const uint4*)(Ap + ka);
            pa[1] = *(const uint4*)(Ap + (size_t)64 * K + ka);
            const size_t kb = ka * N;
            pb[0] = *(const uint4*)(Bp + kb);
            pb[1] = *(const uint4*)(Bp + kb + 8);
        }

        #pragma unroll
        for (int kk = 0; kk < 2; kk++) {
            uint32_t a[4][4], b[4][2];
            const int arow = wm * 64 + (lane & 15);
            const int acol = kk * 16 + (lane >> 4) * 8;
            #pragma unroll
            for (int mt = 0; mt < 4; mt++)
                ldsm4(cvta_smem(&sA[(arow + mt * 16) * A_STR + acol]),
                      a[mt][0], a[mt][1], a[mt][2], a[mt][3]);
            const int brow = kk * 16 + (lane & 15);
            #pragma unroll
            for (int ng = 0; ng < 2; ng++) {
                const int bcol = wn * 32 + ng * 16 + (lane >> 4) * 8;
                ldsm4t(cvta_smem(&sB[brow * B_STR + bcol]),
                       b[2*ng][0], b[2*ng][1], b[2*ng+1][0], b[2*ng+1][1]);
            }
            #pragma unroll
            for (int mt = 0; mt < 4; mt++)
                #pragma unroll
                for (int nt = 0; nt < 4; nt++)
                    mma_fp16(acc[mt][nt], a[mt], b[nt]);
        }
    }

    const int r0 = lane >> 2;
    const int cp = (lane & 3) * 2;
    #pragma unroll
    for (int mt = 0; mt < 4; mt++) {
        #pragma unroll
        for (int nt = 0; nt < 4; nt++) {
            const int gc = bn0 + wn * 32 + nt * 8 + cp;
            const float2 bv = *(const float2*)(bias + gc);
            #pragma unroll
            for (int h = 0; h < 2; h++) {
                const int gr = bm0 + wm * 64 + mt * 16 + r0 + h * 8;
                float ox = acc[mt][nt][2 * h + 0] + bv.x;
                float oy = acc[mt][nt][2 * h + 1] + bv.y;
                float2 rv = *(const float2*)(res + (size_t)gr * N + gc);
                ox += rv.x; oy += rv.y;
                float2 o; o.x = ox; o.y = oy;
                *(float2*)(C + (size_t)gr * N + gc) = o;
            }
        }
    }
}

// ---------------------------------------------------------------------------
// Tensor-core causal flash attention (unchanged from R14).
// ---------------------------------------------------------------------------
#define QTILE 128
#define KTILE 64
#define SROW 72
#define KVBUF (2 * KTILE * SROW)          // 9216 elems = 18,432 B / buffer
#define ASMEM_BYTES (2 * KVBUF * 2)       // 36,864 B

__global__ __launch_bounds__(256) void attn_mma(
    const __half* __restrict__ qkv, __half* __restrict__ outh)
{
    extern __shared__ __align__(16) __half dsm[];

    const int tid  = threadIdx.x;
    const int lane = tid & 31;
    const int warp = tid >> 5;
    const int qt = (SLEN / QTILE - 1) - blockIdx.x;   // heavy blocks first
    const int h  = blockIdx.y;
    const int bz = blockIdx.z;

    const size_t rowstride = QKV_N;
    const size_t batch_row = (size_t)bz * SLEN;

    {
        __half* sQ = dsm;
        for (int i = tid; i < QTILE * 16; i += 256) {
            const int r = i >> 4;
            const int c = (i & 15) * 4;
            const size_t g = (batch_row + qt * QTILE + r) * rowstride + h * HDIM + c;
            *(uint2*)&sQ[r * SROW + c] = *(const uint2*)(qkv + g);
        }
    }
    __syncthreads();

    uint32_t qf[4][4];
    {
        __half* sQ = dsm;
        const __half2 qs = __float2half2_rn(QSCALE_LOG2E);
        const int arow = warp * 16 + (lane & 15);
        #pragma unroll
        for (int ks = 0; ks < 4; ks++) {
            const int acol = ks * 16 + (lane >> 4) * 8;
            ldsm4(cvta_smem(&sQ[arow * SROW + acol]),
                  qf[ks][0], qf[ks][1], qf[ks][2], qf[ks][3]);
            #pragma unroll
            for (int j = 0; j < 4; j++) {
                __half2 v = __hmul2(*(__half2*)&qf[ks][j], qs);
                qf[ks][j] = *(uint32_t*)&v;
            }
        }
    }
    __syncthreads();

    const int base = qt * QTILE + warp * 16;
    const int ktmax_warp = 2 * qt + (warp >= 4 ? 1 : 0);
    const int nkt = 2 * qt + 2;

    uint2 pk[4], pv[4];
    int pr[4], pc[4];
    #pragma unroll
    for (int j = 0; j < 4; j++) {
        const int i = tid + j * 256;
        pr[j] = i >> 4;
        pc[j] = (i & 15) * 4;
    }

    auto prefetch = [&](int kt) {
        #pragma unroll
        for (int j = 0; j < 4; j++) {
            const size_t gk = (batch_row + kt * KTILE + pr[j]) * rowstride
                              + DMODEL + h * HDIM + pc[j];
            pk[j] = *(const uint2*)(qkv + gk);
            pv[j] = *(const uint2*)(qkv + gk + DMODEL);
        }
    };
    auto stash = [&](__half* b) {
        __half* sK = b;
        __half* sV = b + KTILE * SROW;
        #pragma unroll
        for (int j = 0; j < 4; j++) {
            const int o = pr[j] * SROW + pc[j];
            *(uint2*)&sK[o] = pk[j];
            *(uint2*)&sV[o] = pv[j];
        }
    };

    float o[8][4];
    #pragma unroll
    for (int nt = 0; nt < 8; nt++)
        #pragma unroll
        for (int e = 0; e < 4; e++) o[nt][e] = 0.0f;
    float m_a = -1e30f, m_b = -1e30f, l_a = 0.0f, l_b = 0.0f;

    prefetch(0);
    stash(dsm);
    __syncthreads();

    for (int kt = 0; kt < nkt; kt++) {
        __half* buf = dsm + (kt & 1) * KVBUF;
        __half* sK = buf;
        __half* sV = buf + KTILE * SROW;

        if (kt + 1 < nkt) prefetch(kt + 1);

        if (kt <= ktmax_warp) {
            uint32_t s16[8][2];
            #pragma unroll
            for (int nt = 0; nt < 8; nt++) { s16[nt][0] = 0u; s16[nt][1] = 0u; }

            #pragma unroll
            for (int ks = 0; ks < 4; ks++) {
                #pragma unroll
                for (int np = 0; np < 4; np++) {
                    uint32_t k0, k1, k2, k3;
                    const int addr = (np * 16 + (lane & 15)) * SROW
                                     + ks * 16 + (lane >> 4) * 8;
                    ldsm4(cvta_smem(&sK[addr]), k0, k1, k2, k3);
                    uint32_t be[2] = {k0, k2}, bo[2] = {k1, k3};
                    mma_fp16h(s16[2*np],   qf[ks], be);
                    mma_fp16h(s16[2*np+1], qf[ks], bo);
                }
            }

            float s[8][4];
            #pragma unroll
            for (int nt = 0; nt < 8; nt++) {
                float2 lo = __half22float2(*(__half2*)&s16[nt][0]);
                float2 hi = __half22float2(*(__half2*)&s16[nt][1]);
                s[nt][0] = lo.x; s[nt][1] = lo.y;
                s[nt][2] = hi.x; s[nt][3] = hi.y;
            }

            if (kt * KTILE + 63 > base) {
                const int ra = base + (lane >> 2);
                #pragma unroll
                for (int nt = 0; nt < 8; nt++) {
                    const int kc = kt * KTILE + nt * 8 + (lane & 3) * 2;
                    if (kc > ra)      s[nt][0] = -1e30f;
                    if (kc + 1 > ra)  s[nt][1] = -1e30f;
                    if (kc > ra + 8)     s[nt][2] = -1e30f;
                    if (kc + 1 > ra + 8) s[nt][3] = -1e30f;
                }
            }

            float ta = -1e30f, tb = -1e30f;
            #pragma unroll
            for (int nt = 0; nt < 8; nt++) {
                ta = fmaxf(ta, fmaxf(s[nt][0], s[nt][1]));
                tb = fmaxf(tb, fmaxf(s[nt][2], s[nt][3]));
            }
            ta = fmaxf(ta, __shfl_xor_sync(0xffffffffu, ta, 1));
            ta = fmaxf(ta, __shfl_xor_sync(0xffffffffu, ta, 2));
            tb = fmaxf(tb, __shfl_xor_sync(0xffffffffu, tb, 1));
            tb = fmaxf(tb, __shfl_xor_sync(0xffffffffu, tb, 2));

            const float mna = fmaxf(m_a, ta);
            const float mnb = fmaxf(m_b, tb);
            const float ca = exp2f(m_a - mna);
            const float cb = exp2f(m_b - mnb);
            m_a = mna; m_b = mnb;
            l_a *= ca; l_b *= cb;
            #pragma unroll
            for (int nt = 0; nt < 8; nt++) {
                o[nt][0] *= ca; o[nt][1] *= ca;
                o[nt][2] *= cb; o[nt][3] *= cb;
            }

            float sa = 0.0f, sb = 0.0f;
            #pragma unroll
            for (int nt = 0; nt < 8; nt++) {
                float p0 = exp2f(s[nt][0] - mna);
                float p1 = exp2f(s[nt][1] - mna);
                float p2 = exp2f(s[nt][2] - mnb);
                float p3 = exp2f(s[nt][3] - mnb);
                s[nt][0] = p0; s[nt][1] = p1; s[nt][2] = p2; s[nt][3] = p3;
                sa += p0 + p1; sb += p2 + p3;
            }
            sa += __shfl_xor_sync(0xffffffffu, sa, 1);
            sa += __shfl_xor_sync(0xffffffffu, sa, 2);
            sb += __shfl_xor_sync(0xffffffffu, sb, 1);
            sb += __shfl_xor_sync(0xffffffffu, sb, 2);
            l_a += sa; l_b += sb;

            #pragma unroll
            for (int ks = 0; ks < 4; ks++) {
                uint32_t pa[4];
                pa[0] = pack_h2(s[2*ks][0],   s[2*ks][1]);
                pa[1] = pack_h2(s[2*ks][2],   s[2*ks][3]);
                pa[2] = pack_h2(s[2*ks+1][0], s[2*ks+1][1]);
                pa[3] = pack_h2(s[2*ks+1][2], s[2*ks+1][3]);
                #pragma unroll
                for (int np = 0; np < 4; np++) {
                    uint32_t v0, v1, v2, v3;
                    const int addr = (ks * 16 + (lane & 15)) * SROW
                                     + np * 16 + (lane >> 4) * 8;
                    ldsm4t(cvta_smem(&sV[addr]), v0, v1, v2, v3);
                    uint32_t ve[2] = {v0, v1}, vo[2] = {v2, v3};
                    mma_fp16(o[2*np],   pa, ve);
                    mma_fp16(o[2*np+1], pa, vo);
                }
            }
        }

        if (kt + 1 < nkt) stash(dsm + ((kt + 1) & 1) * KVBUF);
        __syncthreads();
    }

    const float ia = 1.0f / l_a;
    const float ib = 1.0f / l_b;
    const int ra = base + (lane >> 2);
    const size_t rowa = (batch_row + ra) * (size_t)DMODEL + h * HDIM;
    const size_t rowb = rowa + 8 * DMODEL;
    #pragma unroll
    for (int nt = 0; nt < 8; nt++) {
        const int col = nt * 8 + (lane & 3) * 2;
        *(uint32_t*)(outh + rowa + col) = pack_h2(o[nt][0] * ia, o[nt][1] * ia);
        *(uint32_t*)(outh + rowb + col) = pack_h2(o[nt][2] * ib, o[nt][3] * ib);
    }
}

// ---------------------------------------------------------------------------
// LayerNorm over last dim, in-place. One block (256 thr) per row of 1024.
// ---------------------------------------------------------------------------
__global__ __launch_bounds__(256) void ln_kernel(
    float* __restrict__ io, const float* __restrict__ gamma,
    const float* __restrict__ beta)
{
    const int row = blockIdx.x;
    const int tid = threadIdx.x;
    float4* p = (float4*)(io + (size_t)row * DMODEL);
    float4 v = p[tid];

    float s  = v.x + v.y + v.z + v.w;
    float s2 = fmaf(v.x, v.x, fmaf(v.y, v.y, fmaf(v.z, v.z, v.w * v.w)));

    #pragma unroll
    for (int ofs = 16; ofs; ofs >>= 1) {
        s  += __shfl_xor_sync(0xffffffffu, s, ofs);
        s2 += __shfl_xor_sync(0xffffffffu, s2, ofs);
    }
    __shared__ float shs[8], shs2[8];
    const int w = tid >> 5, l = tid & 31;
    if (l == 0) { shs[w] = s; shs2[w] = s2; }
    __syncthreads();
    if (tid < 32) {
        float a  = (l < 8) ? shs[l]  : 0.0f;
        float a2 = (l < 8) ? shs2[l] : 0.0f;
        #pragma unroll
        for (int ofs = 4; ofs; ofs >>= 1) {
            a  += __shfl_xor_sync(0xffffffffu, a, ofs);
            a2 += __shfl_xor_sync(0xffffffffu, a2, ofs);
        }
        if (l == 0) { shs[0] = a; shs2[0] = a2; }
    }
    __syncthreads();

    const float mean = shs[0] * (1.0f / DMODEL);
    const float var  = shs2[0] * (1.0f / DMODEL) - mean * mean;
    const float rstd = rsqrtf(var + LN_EPS);

    float4 g  = ((const float4*)gamma)[tid];
    float4 be = ((const float4*)beta)[tid];
    float4 r;
    r.x = (v.x - mean) * rstd * g.x + be.x;
    r.y = (v.y - mean) * rstd * g.y + be.y;
    r.z = (v.z - mean) * rstd * g.z + be.z;
    r.w = (v.w - mean) * rstd * g.w + be.w;
    p[tid] = r;
}

// ---------------------------------------------------------------------------
extern "C" void kernel_launch(void* const* d_in, const int* in_sizes, int n_in,
                              void* d_out, int out_size)
{
    const float* x     = (const float*)d_in[0];
    const float* Wqkv  = (const float*)d_in[1];
    const float* bqkv  = (const float*)d_in[2];
    const float* Wout  = (const float*)d_in[3];
    const float* bout  = (const float*)d_in[4];
    const float* gamma = (const float*)d_in[5];
    const float* beta  = (const float*)d_in[6];
    float* out = (float*)d_out;

    __half *xh, *wq, *wo, *qkv, *attn;
    cudaGetSymbolAddress((void**)&xh,   g_xh);
    cudaGetSymbolAddress((void**)&wq,   g_wqkv);
    cudaGetSymbolAddress((void**)&wo,   g_wout);
    cudaGetSymbolAddress((void**)&qkv,  g_qkv);
    cudaGetSymbolAddress((void**)&attn, g_attn);

    static bool attrs_set = false;
    if (!attrs_set) {
        cudaFuncSetAttribute(mma_gemm_h,
                             cudaFuncAttributeMaxDynamicSharedMemorySize, HGSMEM_BYTES);
        cudaFuncSetAttribute(mma_gemm,
                             cudaFuncAttributeMaxDynamicSharedMemorySize, GSMEM_BYTES);
        cudaFuncSetAttribute(attn_mma,
                             cudaFuncAttributeMaxDynamicSharedMemorySize, ASMEM_BYTES);
        attrs_set = true;
    }

    // 0) fused fp32 -> fp16 conversions (single launch)
    cvt_all_kernel<<<(N4_ALL + 255) / 256, 256>>>(
        (const float4*)x, (const float4*)Wqkv, (const float4*)Wout,
        (uint2*)xh, (uint2*)wq, (uint2*)wo);

    // 1) QKV projection (fp16 accumulators, wide tiles) -> fp16 output
    {
        dim3 grid(QKV_N / HBN, MROWS / BM);
        mma_gemm_h<<<grid, 256, HGSMEM_BYTES>>>(
            xh, wq, bqkv, qkv, MROWS, QKV_N, DMODEL);
    }
    // 2) tensor-core causal flash attention -> fp16 output
    {
        dim3 grid(SLEN / QTILE, NHEADS, BATCH);
        attn_mma<<<grid, 256, ASMEM_BYTES>>>(qkv, attn);
    }
    // 3) out projection + bias + residual -> fp32 (fp32 accumulators)
    {
        dim3 grid(DMODEL / BN, MROWS / BM);
        mma_gemm<<<grid, 256, GSMEM_BYTES>>>(
            attn, wo, bout, x, out, MROWS, DMODEL, DMODEL);
    }
    // 4) LayerNorm in-place on d_out
    ln_kernel<<<MROWS, 256>>>(out, gamma, beta);
}

// round 16
// speedup vs baseline: 1.0680x; 1.0680x over previous
#include <cuda_runtime.h>
#include <cuda_fp16.h>
#include <cstdint>

#define BATCH 8
#define SLEN 1024
#define DMODEL 1024
#define NHEADS 16
#define HDIM 64
#define MROWS (BATCH * SLEN)       // 8192
#define QKV_N (3 * DMODEL)         // 3072
#define LN_EPS 1e-5f
// SM_SCALE * log2(e) folded into Q fragments: scores live in log2 domain.
#define QSCALE_LOG2E 0.045084220f  // 0.03125 * 1.4426950408889634

// Scratch (static device globals: allocation-free rule)
__device__ __half g_xh[(size_t)MROWS * DMODEL];
__device__ __half g_wqkv[(size_t)DMODEL * QKV_N];
__device__ __half g_wout[(size_t)DMODEL * DMODEL];
__device__ __half g_qkv[(size_t)MROWS * QKV_N];
__device__ __half g_attn[(size_t)MROWS * DMODEL];

// ---------------------------------------------------------------------------
// helpers
// ---------------------------------------------------------------------------
__device__ __forceinline__ uint32_t cvta_smem(const void* p) {
    uint32_t a;
    asm("{.reg .u64 t; cvta.to.shared.u64 t, %1; cvt.u32.u64 %0, t;}"
        : "=r"(a) : "l"(p));
    return a;
}
__device__ __forceinline__ void ldsm4(uint32_t a, uint32_t& r0, uint32_t& r1,
                                      uint32_t& r2, uint32_t& r3) {
    asm volatile("ldmatrix.sync.aligned.m8n8.x4.shared.b16 {%0,%1,%2,%3},[%4];"
                 : "=r"(r0), "=r"(r1), "=r"(r2), "=r"(r3) : "r"(a));
}
__device__ __forceinline__ void ldsm4t(uint32_t a, uint32_t& r0, uint32_t& r1,
                                       uint32_t& r2, uint32_t& r3) {
    asm volatile("ldmatrix.sync.aligned.m8n8.x4.trans.shared.b16 {%0,%1,%2,%3},[%4];"
                 : "=r"(r0), "=r"(r1), "=r"(r2), "=r"(r3) : "r"(a));
}
__device__ __forceinline__ void mma_fp16(float* c, const uint32_t* a,
                                         const uint32_t* b) {
    asm volatile(
        "mma.sync.aligned.m16n8k16.row.col.f32.f16.f16.f32 "
        "{%0,%1,%2,%3},{%4,%5,%6,%7},{%8,%9},{%0,%1,%2,%3};"
        : "+f"(c[0]), "+f"(c[1]), "+f"(c[2]), "+f"(c[3])
        : "r"(a[0]), "r"(a[1]), "r"(a[2]), "r"(a[3]), "r"(b[0]), "r"(b[1]));
}
// fp16-accumulator variant (QK^T only)
__device__ __forceinline__ void mma_fp16h(uint32_t* c, const uint32_t* a,
                                          const uint32_t* b) {
    asm volatile(
        "mma.sync.aligned.m16n8k16.row.col.f16.f16.f16.f16 "
        "{%0,%1},{%2,%3,%4,%5},{%6,%7},{%0,%1};"
        : "+r"(c[0]), "+r"(c[1])
        : "r"(a[0]), "r"(a[1]), "r"(a[2]), "r"(a[3]), "r"(b[0]), "r"(b[1]));
}
__device__ __forceinline__ uint32_t pack_h2(float x, float y) {
    __half2 h = __floats2half2_rn(x, y);
    return *(uint32_t*)&h;
}

// ---------------------------------------------------------------------------
// fused fp32 -> fp16 conversion of x, Wqkv, Wout in one launch
// ---------------------------------------------------------------------------
#define N4_X   (MROWS * DMODEL / 4)              // 2,097,152
#define N4_WQ  (DMODEL * QKV_N / 4)              //   786,432
#define N4_WO  (DMODEL * DMODEL / 4)             //   262,144
#define N4_ALL (N4_X + N4_WQ + N4_WO)

__global__ __launch_bounds__(256) void cvt_all_kernel(
    const float4* __restrict__ x, const float4* __restrict__ wq,
    const float4* __restrict__ wo, uint2* __restrict__ xh,
    uint2* __restrict__ wqh, uint2* __restrict__ woh)
{
    int i = blockIdx.x * blockDim.x + threadIdx.x;
    if (i >= N4_ALL) return;
    const float4* src;
    uint2* dst;
    int j;
    if (i < N4_X)            { src = x;  dst = xh;  j = i; }
    else if (i < N4_X + N4_WQ) { src = wq; dst = wqh; j = i - N4_X; }
    else                     { src = wo; dst = woh; j = i - N4_X - N4_WQ; }
    float4 v = src[j];
    uint2 o;
    o.x = pack_h2(v.x, v.y);
    o.y = pack_h2(v.z, v.w);
    dst[j] = o;
}

// ---------------------------------------------------------------------------
// Tensor-core GEMM, fp16 single-MMA, double-buffered smem (1 sync/iter).
// BM=BN=128, BK=32, 8 warps (64x32 warp tiles). 2 CTAs/SM.
// ---------------------------------------------------------------------------
#define BM 128
#define BN 128
#define BK 32
#define A_STR 40        // BK + 8 pad
#define B_STR 136       // BN + 8 pad
#define ABUF (BM * A_STR)                 // 5120 elems
#define BBUF (BK * B_STR)                 // 4352 elems
#define GBUF_ELEMS (ABUF + BBUF)          // 9472 elems = 18,944 B / buffer
#define GSMEM_BYTES (2 * GBUF_ELEMS * 2)  // 37,888 B

template <bool RESID, bool HALF_OUT>
__global__ __launch_bounds__(256, 2) void mma_gemm(
    const __half* __restrict__ Ah, const __half* __restrict__ Bh,
    const float* __restrict__ bias, const float* __restrict__ res,
    float* __restrict__ C, __half* __restrict__ Ch,
    int M, int N, int K)
{
    extern __shared__ __align__(16) __half dsm[];

    const int tid = threadIdx.x;
    const int lane = tid & 31;
    const int warp = tid >> 5;
    const int wm = warp >> 2;
    const int wn = warp & 3;
    const int bm0 = blockIdx.y * BM;
    const int bn0 = blockIdx.x * BN;

    const int ar = tid >> 2;          // 0..63 (rows ar, ar+64)
    const int ac = (tid & 3) * 8;     // k offset
    const int br = tid >> 3;          // 0..31
    const int bc = (tid & 7) * 16;    // n offset

    float acc[4][4][4];
    #pragma unroll
    for (int i = 0; i < 4; i++)
        #pragma unroll
        for (int j = 0; j < 4; j++)
            #pragma unroll
            for (int c = 0; c < 4; c++) acc[i][j][c] = 0.0f;

    const __half* Ap = Ah + (size_t)(bm0 + ar) * K + ac;
    const __half* Bp = Bh + (size_t)br * N + bn0 + bc;

    uint4 pa[2], pb[2];
    pa[0] = *(const uint4*)(Ap);
    pa[1] = *(const uint4*)(Ap + (size_t)64 * K);
    pb[0] = *(const uint4*)(Bp);
    pb[1] = *(const uint4*)(Bp + 8);

    const int iters = K / BK;
    for (int it = 0; it < iters; it++) {
        __half* buf = dsm + (it & 1) * GBUF_ELEMS;
        __half* sA = buf;
        __half* sB = buf + ABUF;
        {   // stage prefetched tile
            uint2* d; const uint2* s;
            d = (uint2*)&sA[ar * A_STR + ac];        s = (const uint2*)&pa[0]; d[0]=s[0]; d[1]=s[1];
            d = (uint2*)&sA[(ar + 64) * A_STR + ac]; s = (const uint2*)&pa[1]; d[0]=s[0]; d[1]=s[1];
            d = (uint2*)&sB[br * B_STR + bc];        s = (const uint2*)&pb[0]; d[0]=s[0]; d[1]=s[1];
            d = (uint2*)&sB[br * B_STR + bc + 8];    s = (const uint2*)&pb[1]; d[0]=s[0]; d[1]=s[1];
        }
        __syncthreads();

        if (it + 1 < iters) {   // prefetch next tile (overlaps with MMAs)
            const size_t ka = (size_t)(it + 1) * BK;
            pa[0] = *(const uint4*)(Ap + ka);
            pa[1] = *(const uint4*)(Ap + (size_t)64 * K + ka);
            const size_t kb = ka * N;
            pb[0] = *(const uint4*)(Bp + kb);
            pb[1] = *(const uint4*)(Bp + kb + 8);
        }

        #pragma unroll
        for (int kk = 0; kk < 2; kk++) {
            uint32_t a[4][4], b[4][2];
            const int arow = wm * 64 + (lane & 15);
            const int acol = kk * 16 + (lane >> 4) * 8;
            #pragma unroll
            for (int mt = 0; mt < 4; mt++)
                ldsm4(cvta_smem(&sA[(arow + mt * 16) * A_STR + acol]),
                      a[mt][0], a[mt][1], a[mt][2], a[mt][3]);
            const int brow = kk * 16 + (lane & 15);
            #pragma unroll
            for (int ng = 0; ng < 2; ng++) {
                const int bcol = wn * 32 + ng * 16 + (lane >> 4) * 8;
                ldsm4t(cvta_smem(&sB[brow * B_STR + bcol]),
                       b[2*ng][0], b[2*ng][1], b[2*ng+1][0], b[2*ng+1][1]);
            }
            #pragma unroll
            for (int mt = 0; mt < 4; mt++)
                #pragma unroll
                for (int nt = 0; nt < 4; nt++)
                    mma_fp16(acc[mt][nt], a[mt], b[nt]);
        }
        // next iter stores to the other buffer; top-of-iter sync orders it.
    }

    const int r0 = lane >> 2;
    const int cp = (lane & 3) * 2;
    #pragma unroll
    for (int mt = 0; mt < 4; mt++) {
        #pragma unroll
        for (int nt = 0; nt < 4; nt++) {
            const int gc = bn0 + wn * 32 + nt * 8 + cp;
            const float2 bv = *(const float2*)(bias + gc);
            #pragma unroll
            for (int h = 0; h < 2; h++) {
                const int gr = bm0 + wm * 64 + mt * 16 + r0 + h * 8;
                float ox = acc[mt][nt][2 * h + 0] + bv.x;
                float oy = acc[mt][nt][2 * h + 1] + bv.y;
                if (HALF_OUT) {
                    *(uint32_t*)(Ch + (size_t)gr * N + gc) = pack_h2(ox, oy);
                } else {
                    if (RESID) {
                        float2 rv = *(const float2*)(res + (size_t)gr * N + gc);
                        ox += rv.x; oy += rv.y;
                    }
                    float2 o; o.x = ox; o.y = oy;
                    *(float2*)(C + (size_t)gr * N + gc) = o;
                }
            }
        }
    }
}

// ---------------------------------------------------------------------------
// Tensor-core causal flash attention. Q pre-scaled by SM_SCALE*log2e, so
// scores are in the log2 domain and softmax uses bare exp2f. QK^T uses
// fp16-acc MMA; PV fp32-acc. Heavy (high-qt) blocks launched first.
// ---------------------------------------------------------------------------
#define QTILE 128
#define KTILE 64
#define SROW 72
#define KVBUF (2 * KTILE * SROW)          // 9216 elems = 18,432 B / buffer
#define ASMEM_BYTES (2 * KVBUF * 2)       // 36,864 B

__global__ __launch_bounds__(256) void attn_mma(
    const __half* __restrict__ qkv, __half* __restrict__ outh)
{
    extern __shared__ __align__(16) __half dsm[];

    const int tid  = threadIdx.x;
    const int lane = tid & 31;
    const int warp = tid >> 5;
    const int qt = (SLEN / QTILE - 1) - blockIdx.x;   // heavy blocks first
    const int h  = blockIdx.y;
    const int bz = blockIdx.z;

    const size_t rowstride = QKV_N;
    const size_t batch_row = (size_t)bz * SLEN;

    // ---- stage Q tile (128 x 64) and grab fragments ----
    {
        __half* sQ = dsm;
        for (int i = tid; i < QTILE * 16; i += 256) {
            const int r = i >> 4;
            const int c = (i & 15) * 4;
            const size_t g = (batch_row + qt * QTILE + r) * rowstride + h * HDIM + c;
            *(uint2*)&sQ[r * SROW + c] = *(const uint2*)(qkv + g);
        }
    }
    __syncthreads();

    uint32_t qf[4][4];
    {
        __half* sQ = dsm;
        const __half2 qs = __float2half2_rn(QSCALE_LOG2E);
        const int arow = warp * 16 + (lane & 15);
        #pragma unroll
        for (int ks = 0; ks < 4; ks++) {
            const int acol = ks * 16 + (lane >> 4) * 8;
            ldsm4(cvta_smem(&sQ[arow * SROW + acol]),
                  qf[ks][0], qf[ks][1], qf[ks][2], qf[ks][3]);
            #pragma unroll
            for (int j = 0; j < 4; j++) {
                __half2 v = __hmul2(*(__half2*)&qf[ks][j], qs);
                qf[ks][j] = *(uint32_t*)&v;
            }
        }
    }
    __syncthreads();   // before K/V staging overwrites the Q region

    const int base = qt * QTILE + warp * 16;
    const int ktmax_warp = 2 * qt + (warp >= 4 ? 1 : 0);
    const int nkt = 2 * qt + 2;

    uint2 pk[4], pv[4];
    int pr[4], pc[4];
    #pragma unroll
    for (int j = 0; j < 4; j++) {
        const int i = tid + j * 256;
        pr[j] = i >> 4;
        pc[j] = (i & 15) * 4;
    }

    auto prefetch = [&](int kt) {
        #pragma unroll
        for (int j = 0; j < 4; j++) {
            const size_t gk = (batch_row + kt * KTILE + pr[j]) * rowstride
                              + DMODEL + h * HDIM + pc[j];
            pk[j] = *(const uint2*)(qkv + gk);
            pv[j] = *(const uint2*)(qkv + gk + DMODEL);
        }
    };
    auto stash = [&](__half* b) {
        __half* sK = b;
        __half* sV = b + KTILE * SROW;
        #pragma unroll
        for (int j = 0; j < 4; j++) {
            const int o = pr[j] * SROW + pc[j];
            *(uint2*)&sK[o] = pk[j];
            *(uint2*)&sV[o] = pv[j];
        }
    };

    float o[8][4];
    #pragma unroll
    for (int nt = 0; nt < 8; nt++)
        #pragma unroll
        for (int e = 0; e < 4; e++) o[nt][e] = 0.0f;
    float m_a = -1e30f, m_b = -1e30f, l_a = 0.0f, l_b = 0.0f;

    prefetch(0);
    stash(dsm);
    __syncthreads();

    for (int kt = 0; kt < nkt; kt++) {
        __half* buf = dsm + (kt & 1) * KVBUF;
        __half* sK = buf;
        __half* sV = buf + KTILE * SROW;

        if (kt + 1 < nkt) prefetch(kt + 1);

        if (kt <= ktmax_warp) {
            // ---- S = (Q*scale) K^T with fp16 accumulators (log2 domain) ----
            uint32_t s16[8][2];
            #pragma unroll
            for (int nt = 0; nt < 8; nt++) { s16[nt][0] = 0u; s16[nt][1] = 0u; }

            #pragma unroll
            for (int ks = 0; ks < 4; ks++) {
                #pragma unroll
                for (int np = 0; np < 4; np++) {
                    uint32_t k0, k1, k2, k3;
                    const int addr = (np * 16 + (lane & 15)) * SROW
                                     + ks * 16 + (lane >> 4) * 8;
                    ldsm4(cvta_smem(&sK[addr]), k0, k1, k2, k3);
                    uint32_t be[2] = {k0, k2}, bo[2] = {k1, k3};
                    mma_fp16h(s16[2*np],   qf[ks], be);
                    mma_fp16h(s16[2*np+1], qf[ks], bo);
                }
            }

            // unpack to fp32
            float s[8][4];
            #pragma unroll
            for (int nt = 0; nt < 8; nt++) {
                float2 lo = __half22float2(*(__half2*)&s16[nt][0]);
                float2 hi = __half22float2(*(__half2*)&s16[nt][1]);
                s[nt][0] = lo.x; s[nt][1] = lo.y;
                s[nt][2] = hi.x; s[nt][3] = hi.y;
            }

            if (kt * KTILE + 63 > base) {
                const int ra = base + (lane >> 2);
                #pragma unroll
                for (int nt = 0; nt < 8; nt++) {
                    const int kc = kt * KTILE + nt * 8 + (lane & 3) * 2;
                    if (kc > ra)      s[nt][0] = -1e30f;
                    if (kc + 1 > ra)  s[nt][1] = -1e30f;
                    if (kc > ra + 8)     s[nt][2] = -1e30f;
                    if (kc + 1 > ra + 8) s[nt][3] = -1e30f;
                }
            }

            float ta = -1e30f, tb = -1e30f;
            #pragma unroll
            for (int nt = 0; nt < 8; nt++) {
                ta = fmaxf(ta, fmaxf(s[nt][0], s[nt][1]));
                tb = fmaxf(tb, fmaxf(s[nt][2], s[nt][3]));
            }
            ta = fmaxf(ta, __shfl_xor_sync(0xffffffffu, ta, 1));
            ta = fmaxf(ta, __shfl_xor_sync(0xffffffffu, ta, 2));
            tb = fmaxf(tb, __shfl_xor_sync(0xffffffffu, tb, 1));
            tb = fmaxf(tb, __shfl_xor_sync(0xffffffffu, tb, 2));

            const float mna = fmaxf(m_a, ta);
            const float mnb = fmaxf(m_b, tb);
            const float ca = exp2f(m_a - mna);
            const float cb = exp2f(m_b - mnb);
            m_a = mna; m_b = mnb;
            l_a *= ca; l_b *= cb;
            #pragma unroll
            for (int nt = 0; nt < 8; nt++) {
                o[nt][0] *= ca; o[nt][1] *= ca;
                o[nt][2] *= cb; o[nt][3] *= cb;
            }

            float sa = 0.0f, sb = 0.0f;
            #pragma unroll
            for (int nt = 0; nt < 8; nt++) {
                float p0 = exp2f(s[nt][0] - mna);
                float p1 = exp2f(s[nt][1] - mna);
                float p2 = exp2f(s[nt][2] - mnb);
                float p3 = exp2f(s[nt][3] - mnb);
                s[nt][0] = p0; s[nt][1] = p1; s[nt][2] = p2; s[nt][3] = p3;
                sa += p0 + p1; sb += p2 + p3;
            }
            sa += __shfl_xor_sync(0xffffffffu, sa, 1);
            sa += __shfl_xor_sync(0xffffffffu, sa, 2);
            sb += __shfl_xor_sync(0xffffffffu, sb, 1);
            sb += __shfl_xor_sync(0xffffffffu, sb, 2);
            l_a += sa; l_b += sb;

            #pragma unroll
            for (int ks = 0; ks < 4; ks++) {
                uint32_t pa[4];
                pa[0] = pack_h2(s[2*ks][0],   s[2*ks][1]);
                pa[1] = pack_h2(s[2*ks][2],   s[2*ks][3]);
                pa[2] = pack_h2(s[2*ks+1][0], s[2*ks+1][1]);
                pa[3] = pack_h2(s[2*ks+1][2], s[2*ks+1][3]);
                #pragma unroll
                for (int np = 0; np < 4; np++) {
                    uint32_t v0, v1, v2, v3;
                    const int addr = (ks * 16 + (lane & 15)) * SROW
                                     + np * 16 + (lane >> 4) * 8;
                    ldsm4t(cvta_smem(&sV[addr]), v0, v1, v2, v3);
                    uint32_t ve[2] = {v0, v1}, vo[2] = {v2, v3};
                    mma_fp16(o[2*np],   pa, ve);
                    mma_fp16(o[2*np+1], pa, vo);
                }
            }
        }

        if (kt + 1 < nkt) stash(dsm + ((kt + 1) & 1) * KVBUF);
        __syncthreads();
    }

    const float ia = 1.0f / l_a;
    const float ib = 1.0f / l_b;
    const int ra = base + (lane >> 2);
    const size_t rowa = (batch_row + ra) * (size_t)DMODEL + h * HDIM;
    const size_t rowb = rowa + 8 * DMODEL;
    #pragma unroll
    for (int nt = 0; nt < 8; nt++) {
        const int col = nt * 8 + (lane & 3) * 2;
        *(uint32_t*)(outh + rowa + col) = pack_h2(o[nt][0] * ia, o[nt][1] * ia);
        *(uint32_t*)(outh + rowb + col) = pack_h2(o[nt][2] * ib, o[nt][3] * ib);
    }
}

// ---------------------------------------------------------------------------
// LayerNorm, in-place: TWO rows per 256-thread block (128 threads per row,
// 8 floats per thread), one barrier amortized across both rows.
// ---------------------------------------------------------------------------
__global__ __launch_bounds__(256) void ln_kernel2(
    float* __restrict__ io, const float* __restrict__ gamma,
    const float* __restrict__ beta)
{
    const int tid = threadIdx.x;
    const int sub = tid >> 7;            // 0/1: which row of the pair
    const int t   = tid & 127;
    const int row = blockIdx.x * 2 + sub;

    float4* p = (float4*)(io + (size_t)row * DMODEL);
    float4 v0 = p[t];
    float4 v1 = p[t + 128];

    float s  = v0.x + v0.y + v0.z + v0.w + v1.x + v1.y + v1.z + v1.w;
    float s2 = fmaf(v0.x, v0.x, fmaf(v0.y, v0.y, fmaf(v0.z, v0.z, v0.w * v0.w)));
    s2 = fmaf(v1.x, v1.x, fmaf(v1.y, v1.y, fmaf(v1.z, v1.z, fmaf(v1.w, v1.w, s2))));

    #pragma unroll
    for (int ofs = 16; ofs; ofs >>= 1) {
        s  += __shfl_xor_sync(0xffffffffu, s, ofs);
        s2 += __shfl_xor_sync(0xffffffffu, s2, ofs);
    }
    __shared__ float shs[2][4], shs2[2][4];
    const int w = (t >> 5);  // warp within row: 0..3
    if ((t & 31) == 0) { shs[sub][w] = s; shs2[sub][w] = s2; }
    __syncthreads();

    const float tot  = shs[sub][0] + shs[sub][1] + shs[sub][2] + shs[sub][3];
    const float tot2 = shs2[sub][0] + shs2[sub][1] + shs2[sub][2] + shs2[sub][3];

    const float mean = tot * (1.0f / DMODEL);
    const float var  = tot2 * (1.0f / DMODEL) - mean * mean;
    const float rstd = rsqrtf(var + LN_EPS);

    float4 g0  = ((const float4*)gamma)[t];
    float4 g1  = ((const float4*)gamma)[t + 128];
    float4 b0  = ((const float4*)beta)[t];
    float4 b1  = ((const float4*)beta)[t + 128];
    float4 r0, r1;
    r0.x = (v0.x - mean) * rstd * g0.x + b0.x;
    r0.y = (v0.y - mean) * rstd * g0.y + b0.y;
    r0.z = (v0.z - mean) * rstd * g0.z + b0.z;
    r0.w = (v0.w - mean) * rstd * g0.w + b0.w;
    r1.x = (v1.x - mean) * rstd * g1.x + b1.x;
    r1.y = (v1.y - mean) * rstd * g1.y + b1.y;
    r1.z = (v1.z - mean) * rstd * g1.z + b1.z;
    r1.w = (v1.w - mean) * rstd * g1.w + b1.w;
    p[t] = r0;
    p[t + 128] = r1;
}

// ---------------------------------------------------------------------------
extern "C" void kernel_launch(void* const* d_in, const int* in_sizes, int n_in,
                              void* d_out, int out_size)
{
    const float* x     = (const float*)d_in[0];
    const float* Wqkv  = (const float*)d_in[1];
    const float* bqkv  = (const float*)d_in[2];
    const float* Wout  = (const float*)d_in[3];
    const float* bout  = (const float*)d_in[4];
    const float* gamma = (const float*)d_in[5];
    const float* beta  = (const float*)d_in[6];
    float* out = (float*)d_out;

    __half *xh, *wq, *wo, *qkv, *attn;
    cudaGetSymbolAddress((void**)&xh,   g_xh);
    cudaGetSymbolAddress((void**)&wq,   g_wqkv);
    cudaGetSymbolAddress((void**)&wo,   g_wout);
    cudaGetSymbolAddress((void**)&qkv,  g_qkv);
    cudaGetSymbolAddress((void**)&attn, g_attn);

    static bool attrs_set = false;
    if (!attrs_set) {
        cudaFuncSetAttribute(mma_gemm<false, true>,
                             cudaFuncAttributeMaxDynamicSharedMemorySize, GSMEM_BYTES);
        cudaFuncSetAttribute(mma_gemm<true, false>,
                             cudaFuncAttributeMaxDynamicSharedMemorySize, GSMEM_BYTES);
        cudaFuncSetAttribute(attn_mma,
                             cudaFuncAttributeMaxDynamicSharedMemorySize, ASMEM_BYTES);
        attrs_set = true;
    }

    // 0) fused fp32 -> fp16 conversions (single launch)
    cvt_all_kernel<<<(N4_ALL + 255) / 256, 256>>>(
        (const float4*)x, (const float4*)Wqkv, (const float4*)Wout,
        (uint2*)xh, (uint2*)wq, (uint2*)wo);

    // 1) QKV projection -> fp16 output
    {
        dim3 grid(QKV_N / BN, MROWS / BM);
        mma_gemm<false, true><<<grid, 256, GSMEM_BYTES>>>(
            xh, wq, bqkv, nullptr, nullptr, qkv, MROWS, QKV_N, DMODEL);
    }
    // 2) tensor-core causal flash attention -> fp16 output
    {
        dim3 grid(SLEN / QTILE, NHEADS, BATCH);
        attn_mma<<<grid, 256, ASMEM_BYTES>>>(qkv, attn);
    }
    // 3) out projection + bias + residual -> fp32
    {
        dim3 grid(DMODEL / BN, MROWS / BM);
        mma_gemm<true, false><<<grid, 256, GSMEM_BYTES>>>(
            attn, wo, bout, x, out, nullptr, MROWS, DMODEL, DMODEL);
    }
    // 4) LayerNorm in-place on d_out (2 rows per block)
    ln_kernel2<<<MROWS / 2, 256>>>(out, gamma, beta);
}